// round 1
// baseline (speedup 1.0000x reference)
#include <cuda_runtime.h>
#include <math.h>

#define ALPHA 0.2f
#define BB   8
#define NN   2048
#define INF  128
#define OUTF 64
#define BN   (BB*NN)   // 16384

// ---------------- scratch (device globals; no allocation allowed) ----------
__device__ float g_xw [BN*OUTF];          // x_w, original order
__device__ float g_s1 [BN];
__device__ float g_s2 [BN];
__device__ float g_E  [BN];               // exp(s2 - c2), original order
__device__ float g_F  [BN];               // exp(a*s2 - c2), original order
__device__ float g_s2s[BN];               // s2 sorted ascending (per batch)
__device__ int   g_perm[BN];              // sorted rank -> original index
__device__ float g_xws[BN*OUTF];          // x_w gathered into sorted order
__device__ float g_SXE[BB*(NN+1)*OUTF];   // suffix sums of E*x_w (sorted order)
__device__ float g_PXF[BB*(NN+1)*OUTF];   // prefix sums of F*x_w
__device__ float g_SE [BB*(NN+1)];        // scalar suffix sums of E
__device__ float g_PF [BB*(NN+1)];        // scalar prefix sums of F
__device__ float g_c1 [BB];
__device__ float g_c2 [BB];
__device__ float g_An [BN];               // A_i * invZ_i
__device__ float g_Bn [BN];               // B_i * invZ_i

// ---------------- K1: x_w = inputs @ W ; s1, s2 ----------------------------
__global__ void k1_xw(const float* __restrict__ in,
                      const float* __restrict__ emb,
                      const float* __restrict__ W,
                      const float* __restrict__ a)
{
    __shared__ float sW[INF*OUTF];     // 32 KB
    __shared__ float sa[4*OUTF];       // 1 KB
    __shared__ float sin_[4][INF];     // 2 KB
    __shared__ float sr1[4][2], sr2[4][2];

    int tid = threadIdx.x;
    for (int i = tid; i < INF*OUTF; i += 256) sW[i] = W[i];
    sa[tid] = a[tid];                  // blockDim == 256 == 4*OUTF
    int node0 = blockIdx.x * 4;
    for (int i = tid; i < 4*INF; i += 256) {
        int g = i / INF, k = i % INF;
        sin_[g][k] = in[(node0+g)*INF + k];
    }
    __syncthreads();

    int g = tid >> 6;        // node within CTA (0..3)
    int f = tid & 63;
    int node = node0 + g;

    float acc = 0.f;
#pragma unroll
    for (int k = 0; k < INF; k++)
        acc = fmaf(sin_[g][k], sW[k*OUTF + f], acc);
    g_xw[node*OUTF + f] = acc;

    float e = emb[node*OUTF + f];
    float c1 = e*sa[f]       + acc*sa[64  + f];
    float c2 = e*sa[128 + f] + acc*sa[192 + f];
#pragma unroll
    for (int o = 16; o > 0; o >>= 1) {
        c1 += __shfl_down_sync(0xffffffffu, c1, o);
        c2 += __shfl_down_sync(0xffffffffu, c2, o);
    }
    int lane = tid & 31, w2 = (tid >> 5) & 1;
    if (lane == 0) { sr1[g][w2] = c1; sr2[g][w2] = c2; }
    __syncthreads();
    if (f == 0) {
        g_s1[node] = sr1[g][0] + sr1[g][1];
        g_s2[node] = sr2[g][0] + sr2[g][1];
    }
}

// ---------------- K2: per-batch maxes, E/F, bitonic sort of s2 -------------
__device__ __forceinline__ float block_max_1024(float v, float* sred)
{
    __syncthreads();
#pragma unroll
    for (int o = 16; o > 0; o >>= 1)
        v = fmaxf(v, __shfl_xor_sync(0xffffffffu, v, o));
    int lane = threadIdx.x & 31, w = threadIdx.x >> 5;
    if (lane == 0) sred[w] = v;
    __syncthreads();
    if (threadIdx.x < 32) {
        float x = sred[threadIdx.x];
#pragma unroll
        for (int o = 16; o > 0; o >>= 1)
            x = fmaxf(x, __shfl_xor_sync(0xffffffffu, x, o));
        if (threadIdx.x == 0) sred[0] = x;
    }
    __syncthreads();
    return sred[0];
}

__global__ void k2_sort()
{
    __shared__ float key[NN];    // 8 KB
    __shared__ int   sidx[NN];   // 8 KB
    __shared__ float sred[32];

    int b = blockIdx.x, tid = threadIdx.x;

    float m1 = -3.4e38f, m2 = -3.4e38f;
    for (int i = tid; i < NN; i += 1024) {
        m1 = fmaxf(m1, g_s1[b*NN + i]);
        float v = g_s2[b*NN + i];
        key[i] = v; sidx[i] = i;
        m2 = fmaxf(m2, v);
    }
    float c1 = block_max_1024(m1, sred);
    float c2 = block_max_1024(m2, sred);
    if (tid == 0) { g_c1[b] = c1; g_c2[b] = c2; }

    // E/F in original order (before sort scrambles key[])
    for (int i = tid; i < NN; i += 1024) {
        float v = key[i];
        g_E[b*NN + i] = expf(v - c2);
        g_F[b*NN + i] = expf(ALPHA*v - c2);
    }
    __syncthreads();

    // bitonic sort ascending, 2048 elements
    for (int k = 2; k <= NN; k <<= 1) {
        for (int j = k >> 1; j > 0; j >>= 1) {
            for (int i = tid; i < NN; i += 1024) {
                int p = i ^ j;
                if (p > i) {
                    bool up = ((i & k) == 0);
                    float a0 = key[i], a1 = key[p];
                    if ((a0 > a1) == up) {
                        key[i] = a1; key[p] = a0;
                        int t = sidx[i]; sidx[i] = sidx[p]; sidx[p] = t;
                    }
                }
            }
            __syncthreads();
        }
    }
    for (int i = tid; i < NN; i += 1024) {
        g_s2s [b*NN + i] = key[i];
        g_perm[b*NN + i] = sidx[i];
    }
}

// ---------------- K2b: gather x_w into sorted order ------------------------
__global__ void k2b_gather()
{
    int id = blockIdx.x * 256 + threadIdx.x;     // BN*OUTF total
    int f = id & 63;
    int r = (id >> 6) & (NN - 1);
    int b = id >> 17;                             // 2048*64 = 2^17
    g_xws[id] = g_xw[((size_t)b*NN + g_perm[b*NN + r])*OUTF + f];
}

// ---------------- K2c: chunked suffix/prefix scans -------------------------
__global__ void k2c_scan()
{
    __shared__ float Es[NN], Fs[NN];       // 16 KB
    __shared__ float Ssum[16][64];         // 4 KB
    __shared__ float sSE[16], sSF[16];

    int b = blockIdx.x, tid = threadIdx.x;
    float c2 = g_c2[b];
    for (int i = tid; i < NN; i += 1024) {
        float v = g_s2s[b*NN + i];
        Es[i] = expf(v - c2);
        Fs[i] = expf(ALPHA*v - c2);
    }
    __syncthreads();

    int c = tid >> 6, f = tid & 63;        // 16 chunks x 64 features
    const float* xws = g_xws + (size_t)b*NN*OUTF;
    float* SXE = g_SXE + (size_t)b*(NN+1)*OUTF;
    float* PXF = g_PXF + (size_t)b*(NN+1)*OUTF;
    int r0 = c * 128;

    // --- E suffix (vector) ---
    float acc = 0.f;
#pragma unroll 8
    for (int r = r0; r < r0 + 128; r++) acc = fmaf(Es[r], xws[r*64 + f], acc);
    Ssum[c][f] = acc;
    __syncthreads();
    float off = 0.f;
    for (int cc = c + 1; cc < 16; cc++) off += Ssum[cc][f];
    if (c == 15) SXE[NN*64 + f] = 0.f;
    float a2 = off;
#pragma unroll 8
    for (int r = r0 + 127; r >= r0; r--) {
        a2 = fmaf(Es[r], xws[r*64 + f], a2);
        SXE[r*64 + f] = a2;
    }
    __syncthreads();

    // --- F prefix (vector) ---
    acc = 0.f;
#pragma unroll 8
    for (int r = r0; r < r0 + 128; r++) acc = fmaf(Fs[r], xws[r*64 + f], acc);
    Ssum[c][f] = acc;
    __syncthreads();
    off = 0.f;
    for (int cc = 0; cc < c; cc++) off += Ssum[cc][f];
    if (c == 0) PXF[f] = 0.f;
    a2 = off;
#pragma unroll 8
    for (int r = r0; r < r0 + 128; r++) {
        a2 = fmaf(Fs[r], xws[r*64 + f], a2);
        PXF[(r+1)*64 + f] = a2;
    }
    __syncthreads();

    // --- scalar scans ---
    if (tid < 16) {
        float s = 0.f;
        for (int r = tid*128; r < tid*128 + 128; r++) s += Es[r];
        sSE[tid] = s;
    } else if (tid < 32) {
        int cc = tid - 16;
        float s = 0.f;
        for (int r = cc*128; r < cc*128 + 128; r++) s += Fs[r];
        sSF[cc] = s;
    }
    __syncthreads();
    if (tid < 16) {
        float o = 0.f;
        for (int cc = tid + 1; cc < 16; cc++) o += sSE[cc];
        float* SE = g_SE + (size_t)b*(NN+1);
        if (tid == 15) SE[NN] = 0.f;
        float aa = o;
        for (int r = tid*128 + 127; r >= tid*128; r--) { aa += Es[r]; SE[r] = aa; }
    } else if (tid < 32) {
        int cc = tid - 16;
        float o = 0.f;
        for (int c3 = 0; c3 < cc; c3++) o += sSF[c3];
        float* PF = g_PF + (size_t)b*(NN+1);
        if (cc == 0) PF[0] = 0.f;
        float aa = o;
        for (int r = cc*128; r < cc*128 + 128; r++) { aa += Fs[r]; PF[r+1] = aa; }
    }
}

// ---------------- K3: search + Z + h_prime ---------------------------------
__global__ void k3_hprime(float* __restrict__ out_h)
{
    __shared__ float s2s[NN];     // 8 KB
    int tid = threadIdx.x;
    int i0 = blockIdx.x * 4;
    int b = i0 / NN;
    for (int i = tid; i < NN; i += 256) s2s[i] = g_s2s[b*NN + i];
    __syncthreads();

    int g = tid >> 6, f = tid & 63;
    int node = i0 + g;
    float s1 = g_s1[node];
    float t = -s1;
    int lo = 0, hi = NN;
    while (lo < hi) { int mid = (lo + hi) >> 1; if (s2s[mid] < t) lo = mid + 1; else hi = mid; }
    int k = lo;

    float c1 = g_c1[b];
    float A  = expf(s1 - c1);
    float Bv = expf(ALPHA*s1 - c1);
    float Z  = A * g_SE[(size_t)b*(NN+1) + k] + Bv * g_PF[(size_t)b*(NN+1) + k];
    float invZ = 1.0f / Z;

    size_t base = ((size_t)b*(NN+1) + k) * OUTF + f;
    float h = invZ * (A * g_SXE[base] + Bv * g_PXF[base]);
    out_h[(size_t)node*OUTF + f] = fmaxf(h, 0.f);
    if (f == 0) { g_An[node] = A * invZ; g_Bn[node] = Bv * invZ; }
}

// ---------------- K4: attention write (store-bound) ------------------------
__global__ void k4_att(float* __restrict__ out_att)
{
    __shared__ float sE[NN], sF[NN], ss2[NN];   // 24 KB
    int tid = threadIdx.x;
    int i0 = blockIdx.x * 8;
    int b = i0 / NN;
    for (int i = tid; i < NN; i += 256) {
        sE[i]  = g_E [b*NN + i];
        sF[i]  = g_F [b*NN + i];
        ss2[i] = g_s2[b*NN + i];
    }
    __syncthreads();

#pragma unroll
    for (int g = 0; g < 8; g++) {
        int node = i0 + g;
        float Ai = g_An[node], Bi = g_Bn[node];
        float t  = -g_s1[node];
        float4* dst = reinterpret_cast<float4*>(out_att + (size_t)node * NN);
#pragma unroll
        for (int j4 = tid; j4 < NN/4; j4 += 256) {
            int j = j4 * 4;
            float4 o;
            o.x = (ss2[j+0] >= t) ? Ai*sE[j+0] : Bi*sF[j+0];
            o.y = (ss2[j+1] >= t) ? Ai*sE[j+1] : Bi*sF[j+1];
            o.z = (ss2[j+2] >= t) ? Ai*sE[j+2] : Bi*sF[j+2];
            o.w = (ss2[j+3] >= t) ? Ai*sE[j+3] : Bi*sF[j+3];
            dst[j4] = o;
        }
    }
}

// ---------------- launch ----------------------------------------------------
extern "C" void kernel_launch(void* const* d_in, const int* in_sizes, int n_in,
                              void* d_out, int out_size)
{
    const float* in  = (const float*)d_in[0];   // (8,2048,128)
    const float* emb = (const float*)d_in[1];   // (8,2048,64)
    const float* W   = (const float*)d_in[2];   // (128,64)
    const float* a   = (const float*)d_in[3];   // (256,1)

    float* out    = (float*)d_out;
    float* out_h  = out;                          // relu(h_prime): BN*OUTF
    float* out_at = out + (size_t)BN*OUTF;        // attention:     BN*NN

    k1_xw   <<<BN/4,        256 >>>(in, emb, W, a);
    k2_sort <<<BB,          1024>>>();
    k2b_gather<<<BN*OUTF/256,256>>>();
    k2c_scan<<<BB,          1024>>>();
    k3_hprime<<<BN/4,       256 >>>(out_h);
    k4_att  <<<BN/8,        256 >>>(out_at);
}

// round 2
// speedup vs baseline: 1.1883x; 1.1883x over previous
#include <cuda_runtime.h>
#include <math.h>

#define ALPHA 0.2f
#define BB   8
#define NN   2048
#define INF  128
#define OUTF 64
#define BN   (BB*NN)   // 16384

#define CHUNKS 16      // chunks per batch for hierarchical scan
#define CROWS  128     // rows per chunk
#define GROUPS 4       // thread groups per chunk CTA
#define GROWS  32      // rows per thread in scan

// ---------------- scratch (device globals; no allocation allowed) ----------
__device__ float g_xw [BN*OUTF];          // x_w, original order
__device__ float g_s1 [BN];
__device__ float g_s2 [BN];
__device__ float g_E  [BN];               // exp(s2 - c2), original order
__device__ float g_F  [BN];               // exp(a*s2 - c2), original order
__device__ float g_s2s[BN];               // s2 sorted ascending (per batch)
__device__ int   g_perm[BN];              // sorted rank -> original index
__device__ float g_xws[BN*OUTF];          // x_w gathered into sorted order
__device__ float g_SXE[BB*(NN+1)*OUTF];   // suffix sums of E*x_w (sorted order)
__device__ float g_PXF[BB*(NN+1)*OUTF];   // prefix sums of F*x_w (exclusive at index)
__device__ float g_CSE[BB*CHUNKS*OUTF];   // per-chunk vector sums (E)
__device__ float g_CSF[BB*CHUNKS*OUTF];   // per-chunk vector sums (F)
__device__ float g_prefE[BB*(NN+1)];      // scalar exclusive prefix of E (sorted)
__device__ float g_prefF[BB*(NN+1)];      // scalar exclusive prefix of F (sorted)
__device__ float g_c1 [BB];
__device__ float g_c2 [BB];
__device__ float g_An [BN];               // A_i * invZ_i
__device__ float g_Bn [BN];               // B_i * invZ_i

// ---------------- K1: x_w = inputs @ W ; s1, s2  (16 nodes / CTA) ----------
__global__ void k1_xw(const float* __restrict__ in,
                      const float* __restrict__ emb,
                      const float* __restrict__ W,
                      const float* __restrict__ a)
{
    __shared__ float sW[INF*OUTF];        // 32 KB
    __shared__ float sa[4*OUTF];          // 1 KB
    __shared__ float sin_[16][INF];       // 8 KB
    __shared__ float sr1[16][2], sr2[16][2];

    int tid = threadIdx.x;
    for (int i = tid; i < INF*OUTF; i += 256) sW[i] = W[i];
    sa[tid] = a[tid];
    int node0 = blockIdx.x * 16;
    for (int i = tid; i < 16*INF; i += 256) {
        int g = i >> 7, k = i & 127;
        sin_[g][k] = in[(size_t)(node0+g)*INF + k];
    }
    __syncthreads();

    int gq = tid >> 6, f = tid & 63;
    int lane = tid & 31, w2 = (tid >> 5) & 1;

#pragma unroll
    for (int ng = 0; ng < 4; ng++) {
        int g = ng*4 + gq;
        int node = node0 + g;
        float acc = 0.f;
#pragma unroll
        for (int k = 0; k < INF; k++)
            acc = fmaf(sin_[g][k], sW[k*OUTF + f], acc);
        g_xw[(size_t)node*OUTF + f] = acc;

        float e = emb[(size_t)node*OUTF + f];
        float c1 = e*sa[f]       + acc*sa[64  + f];
        float c2 = e*sa[128 + f] + acc*sa[192 + f];
#pragma unroll
        for (int o = 16; o > 0; o >>= 1) {
            c1 += __shfl_down_sync(0xffffffffu, c1, o);
            c2 += __shfl_down_sync(0xffffffffu, c2, o);
        }
        if (lane == 0) { sr1[g][w2] = c1; sr2[g][w2] = c2; }
    }
    __syncthreads();
    if (tid < 16) {
        g_s1[node0 + tid] = sr1[tid][0] + sr1[tid][1];
        g_s2[node0 + tid] = sr2[tid][0] + sr2[tid][1];
    }
}

// ---------------- K2: per-batch maxes, E/F, bitonic sort of s2 -------------
__device__ __forceinline__ float block_max_1024(float v, float* sred)
{
    __syncthreads();
#pragma unroll
    for (int o = 16; o > 0; o >>= 1)
        v = fmaxf(v, __shfl_xor_sync(0xffffffffu, v, o));
    int lane = threadIdx.x & 31, w = threadIdx.x >> 5;
    if (lane == 0) sred[w] = v;
    __syncthreads();
    if (threadIdx.x < 32) {
        float x = sred[threadIdx.x];
#pragma unroll
        for (int o = 16; o > 0; o >>= 1)
            x = fmaxf(x, __shfl_xor_sync(0xffffffffu, x, o));
        if (threadIdx.x == 0) sred[0] = x;
    }
    __syncthreads();
    return sred[0];
}

__global__ void k2_sort()
{
    __shared__ float key[NN];    // 8 KB
    __shared__ int   sidx[NN];   // 8 KB
    __shared__ float sred[32];

    int b = blockIdx.x, tid = threadIdx.x;

    float m1 = -3.4e38f, m2 = -3.4e38f;
    for (int i = tid; i < NN; i += 1024) {
        m1 = fmaxf(m1, g_s1[b*NN + i]);
        float v = g_s2[b*NN + i];
        key[i] = v; sidx[i] = i;
        m2 = fmaxf(m2, v);
    }
    float c1 = block_max_1024(m1, sred);
    float c2 = block_max_1024(m2, sred);
    if (tid == 0) { g_c1[b] = c1; g_c2[b] = c2; }

    // E/F in original order (before sort scrambles key[])
    for (int i = tid; i < NN; i += 1024) {
        float v = key[i];
        g_E[b*NN + i] = expf(v - c2);
        g_F[b*NN + i] = expf(ALPHA*v - c2);
    }
    __syncthreads();

    // bitonic sort ascending, 2048 elements
    for (int k = 2; k <= NN; k <<= 1) {
        for (int j = k >> 1; j > 0; j >>= 1) {
            for (int i = tid; i < NN; i += 1024) {
                int p = i ^ j;
                if (p > i) {
                    bool up = ((i & k) == 0);
                    float a0 = key[i], a1 = key[p];
                    if ((a0 > a1) == up) {
                        key[i] = a1; key[p] = a0;
                        int t = sidx[i]; sidx[i] = sidx[p]; sidx[p] = t;
                    }
                }
            }
            __syncthreads();
        }
    }
    for (int i = tid; i < NN; i += 1024) {
        g_s2s [b*NN + i] = key[i];
        g_perm[b*NN + i] = sidx[i];
    }
}

// ---------------- K2b: gather x_w into sorted order ------------------------
__global__ void k2b_gather()
{
    int id = blockIdx.x * 256 + threadIdx.x;     // BN*OUTF total
    int f = id & 63;
    int r = (id >> 6) & (NN - 1);
    int b = id >> 17;
    g_xws[id] = g_xw[((size_t)b*NN + g_perm[b*NN + r])*OUTF + f];
}

// ---------------- kA: per-chunk vector partial sums ------------------------
__global__ void kA_partial()
{
    __shared__ float Es[CROWS], Fs[CROWS];
    __shared__ float psE[GROUPS][OUTF], psF[GROUPS][OUTF];
    int b = blockIdx.y, c = blockIdx.x, tid = threadIdx.x;
    float c2 = g_c2[b];
    if (tid < CROWS) {
        float v = g_s2s[b*NN + c*CROWS + tid];
        Es[tid] = expf(v - c2);
        Fs[tid] = expf(ALPHA*v - c2);
    }
    __syncthreads();
    int g = tid >> 6, f = tid & 63;
    const float* xws = g_xws + ((size_t)b*NN + c*CROWS) * OUTF;
    float aE = 0.f, aF = 0.f;
    int r0 = g * GROWS;
#pragma unroll 8
    for (int r = r0; r < r0 + GROWS; r++) {
        float x = xws[r*OUTF + f];
        aE = fmaf(Es[r], x, aE);
        aF = fmaf(Fs[r], x, aF);
    }
    psE[g][f] = aE; psF[g][f] = aF;
    __syncthreads();
    if (tid < OUTF) {
        g_CSE[(b*CHUNKS + c)*OUTF + tid] = psE[0][tid]+psE[1][tid]+psE[2][tid]+psE[3][tid];
        g_CSF[(b*CHUNKS + c)*OUTF + tid] = psF[0][tid]+psF[1][tid]+psF[2][tid]+psF[3][tid];
    }
}

// ---------------- kB: scalar exclusive prefix scans (E, F per batch) -------
__global__ void kB_scalar()
{
    __shared__ float wsE[8], wsF[8];
    int b = blockIdx.x, tid = threadIdx.x;
    float c2 = g_c2[b];
    float ev[8], fv[8];
    float sE = 0.f, sF = 0.f;
    int base = b*NN + tid*8;
#pragma unroll
    for (int r = 0; r < 8; r++) {
        float v = g_s2s[base + r];
        ev[r] = expf(v - c2); fv[r] = expf(ALPHA*v - c2);
        sE += ev[r]; sF += fv[r];
    }
    float iE = sE, iF = sF;
    int lane = tid & 31, warp = tid >> 5;
#pragma unroll
    for (int o = 1; o < 32; o <<= 1) {
        float tE = __shfl_up_sync(0xffffffffu, iE, o);
        float tF = __shfl_up_sync(0xffffffffu, iF, o);
        if (lane >= o) { iE += tE; iF += tF; }
    }
    if (lane == 31) { wsE[warp] = iE; wsF[warp] = iF; }
    __syncthreads();
    float wOffE = 0.f, wOffF = 0.f;
#pragma unroll
    for (int w = 0; w < 8; w++)
        if (w < warp) { wOffE += wsE[w]; wOffF += wsF[w]; }
    float rE = wOffE + iE - sE;   // exclusive offset for this thread
    float rF = wOffF + iF - sF;
    float* pE = g_prefE + (size_t)b*(NN+1);
    float* pF = g_prefF + (size_t)b*(NN+1);
#pragma unroll
    for (int r = 0; r < 8; r++) {
        pE[tid*8 + r] = rE; pF[tid*8 + r] = rF;
        rE += ev[r]; rF += fv[r];
    }
    if (tid == 255) { pE[NN] = rE; pF[NN] = rF; }
}

// ---------------- kC: final scan → SXE (suffix E*x), PXF (prefix F*x) ------
__global__ void kC_scan()
{
    __shared__ float Es[CROWS], Fs[CROWS];
    __shared__ float psE[GROUPS][OUTF], psF[GROUPS][OUTF];
    int b = blockIdx.y, c = blockIdx.x, tid = threadIdx.x;
    float c2 = g_c2[b];
    if (tid < CROWS) {
        float v = g_s2s[b*NN + c*CROWS + tid];
        Es[tid] = expf(v - c2);
        Fs[tid] = expf(ALPHA*v - c2);
    }
    __syncthreads();
    int g = tid >> 6, f = tid & 63;
    const float* xws = g_xws + ((size_t)b*NN + c*CROWS) * OUTF;
    float aE = 0.f, aF = 0.f;
    int r0 = g * GROWS;
#pragma unroll 8
    for (int r = r0; r < r0 + GROWS; r++) {
        float x = xws[r*OUTF + f];
        aE = fmaf(Es[r], x, aE);
        aF = fmaf(Fs[r], x, aF);
    }
    psE[g][f] = aE; psF[g][f] = aF;
    __syncthreads();

    float offE = 0.f, offF = 0.f, totE = 0.f, totF = 0.f;
#pragma unroll
    for (int cc = 0; cc < CHUNKS; cc++) {
        float vE = g_CSE[(b*CHUNKS + cc)*OUTF + f];
        float vF = g_CSF[(b*CHUNKS + cc)*OUTF + f];
        totE += vE; totF += vF;
        if (cc < c) { offE += vE; offF += vF; }
    }
#pragma unroll
    for (int gg = 0; gg < GROUPS-1; gg++)
        if (gg < g) { offE += psE[gg][f]; offF += psF[gg][f]; }

    float* SXE = g_SXE + (size_t)b*(NN+1)*OUTF;
    float* PXF = g_PXF + (size_t)b*(NN+1)*OUTF;
    float runE = offE, runF = offF;
#pragma unroll 8
    for (int r = r0; r < r0 + GROWS; r++) {
        int R = c*CROWS + r;
        float x = xws[r*OUTF + f];
        SXE[(size_t)R*OUTF + f] = totE - runE;   // suffix including row R
        runE = fmaf(Es[r], x, runE);
        runF = fmaf(Fs[r], x, runF);
        PXF[(size_t)(R+1)*OUTF + f] = runF;      // prefix through row R
    }
    if (c == CHUNKS-1 && tid < OUTF) SXE[(size_t)NN*OUTF + tid] = 0.f;
    if (c == 0 && tid < OUTF)        PXF[tid] = 0.f;
}

// ---------------- K3: search + Z + h_prime  (16 nodes / CTA) ---------------
__global__ void k3_hprime(float* __restrict__ out_h)
{
    __shared__ float s2s[NN];     // 8 KB
    int tid = threadIdx.x;
    int i0 = blockIdx.x * 16;
    int b = i0 / NN;
    for (int i = tid; i < NN; i += 256) s2s[i] = g_s2s[b*NN + i];
    __syncthreads();

    int gq = tid >> 6, f = tid & 63;
    float c1 = g_c1[b];
    const float* pE = g_prefE + (size_t)b*(NN+1);
    const float* pF = g_prefF + (size_t)b*(NN+1);
    float totE = pE[NN];

#pragma unroll
    for (int ng = 0; ng < 4; ng++) {
        int node = i0 + ng*4 + gq;
        float s1 = g_s1[node];
        float t = -s1;
        int lo = 0, hi = NN;
        while (lo < hi) { int mid = (lo + hi) >> 1; if (s2s[mid] < t) lo = mid + 1; else hi = mid; }
        int k = lo;

        float A  = expf(s1 - c1);
        float Bv = expf(ALPHA*s1 - c1);
        float Z  = A * (totE - pE[k]) + Bv * pF[k];
        float invZ = 1.0f / Z;

        size_t base = ((size_t)b*(NN+1) + k) * OUTF + f;
        float h = invZ * (A * g_SXE[base] + Bv * g_PXF[base]);
        out_h[(size_t)node*OUTF + f] = fmaxf(h, 0.f);
        if (f == 0) { g_An[node] = A * invZ; g_Bn[node] = Bv * invZ; }
    }
}

// ---------------- K4: attention write (store-bound, 16 nodes / CTA) --------
__global__ void k4_att(float* __restrict__ out_att)
{
    __shared__ float sE[NN], sF[NN], ss2[NN];   // 24 KB
    int tid = threadIdx.x;
    int i0 = blockIdx.x * 16;
    int b = i0 / NN;
    for (int i = tid; i < NN; i += 256) {
        sE[i]  = g_E [b*NN + i];
        sF[i]  = g_F [b*NN + i];
        ss2[i] = g_s2[b*NN + i];
    }
    __syncthreads();

#pragma unroll
    for (int g = 0; g < 16; g++) {
        int node = i0 + g;
        float Ai = g_An[node], Bi = g_Bn[node];
        float t  = -g_s1[node];
        float4* dst = reinterpret_cast<float4*>(out_att + (size_t)node * NN);
#pragma unroll 2
        for (int j4 = tid; j4 < NN/4; j4 += 256) {
            int j = j4 * 4;
            float4 o;
            o.x = (ss2[j+0] >= t) ? Ai*sE[j+0] : Bi*sF[j+0];
            o.y = (ss2[j+1] >= t) ? Ai*sE[j+1] : Bi*sF[j+1];
            o.z = (ss2[j+2] >= t) ? Ai*sE[j+2] : Bi*sF[j+2];
            o.w = (ss2[j+3] >= t) ? Ai*sE[j+3] : Bi*sF[j+3];
            dst[j4] = o;
        }
    }
}

// ---------------- launch ----------------------------------------------------
extern "C" void kernel_launch(void* const* d_in, const int* in_sizes, int n_in,
                              void* d_out, int out_size)
{
    const float* in  = (const float*)d_in[0];   // (8,2048,128)
    const float* emb = (const float*)d_in[1];   // (8,2048,64)
    const float* W   = (const float*)d_in[2];   // (128,64)
    const float* a   = (const float*)d_in[3];   // (256,1)

    float* out    = (float*)d_out;
    float* out_h  = out;                          // relu(h_prime): BN*OUTF
    float* out_at = out + (size_t)BN*OUTF;        // attention:     BN*NN

    k1_xw     <<<BN/16,           256 >>>(in, emb, W, a);
    k2_sort   <<<BB,              1024>>>();
    k2b_gather<<<BN*OUTF/256,     256 >>>();
    kA_partial<<<dim3(CHUNKS,BB), 256 >>>();
    kB_scalar <<<BB,              256 >>>();
    kC_scan   <<<dim3(CHUNKS,BB), 256 >>>();
    k3_hprime <<<BN/16,           256 >>>(out_h);
    k4_att    <<<BN/16,           256 >>>(out_at);
}

// round 3
// speedup vs baseline: 1.2785x; 1.0758x over previous
#include <cuda_runtime.h>
#include <math.h>
#include <stdint.h>

#define ALPHA 0.2f
#define BB   8
#define NN   2048
#define INF  128
#define OUTF 64
#define BN   (BB*NN)   // 16384

#define CHUNKS 32      // chunks per batch for hierarchical scan
#define CROWS  64      // rows per chunk
#define GROWS  16      // rows per thread in scan

// ---------------- scratch (device globals; no allocation allowed) ----------
__device__ float g_xw [BN*OUTF];          // x_w, original order
__device__ float g_s1 [BN];
__device__ float g_s2 [BN];
__device__ float g_E  [BN];               // exp(s2 - c2), original order
__device__ float g_F  [BN];               // exp(a*s2 - c2), original order
__device__ float g_s2s[BN];               // s2 sorted ascending (per batch)
__device__ int   g_perm[BN];              // sorted rank -> original index
__device__ float g_SXE[BB*(NN+1)*OUTF];   // suffix sums of E*x_w (sorted order)
__device__ float g_PXF[BB*(NN+1)*OUTF];   // prefix sums of F*x_w (exclusive)
__device__ float g_CSE[BB*CHUNKS*OUTF];   // per-chunk vector sums (E)
__device__ float g_CSF[BB*CHUNKS*OUTF];   // per-chunk vector sums (F)
__device__ float g_c2 [BB];
__device__ float g_An [BN];               // A_i * invZ_i
__device__ float g_Bn [BN];               // B_i * invZ_i
__device__ int   g_ki [BN];               // split index per node

// ---------------- K1: x_w = inputs @ W ; s1, s2  (16 nodes / CTA) ----------
__global__ void k1_xw(const float* __restrict__ in,
                      const float* __restrict__ emb,
                      const float* __restrict__ W,
                      const float* __restrict__ a)
{
    __shared__ float sW[INF*OUTF];        // 32 KB
    __shared__ float sa[4*OUTF];          // 1 KB
    __shared__ float sin_[16][INF];       // 8 KB
    __shared__ float sr1[16][2], sr2[16][2];

    int tid = threadIdx.x;
    for (int i = tid; i < INF*OUTF; i += 256) sW[i] = W[i];
    sa[tid] = a[tid];
    int node0 = blockIdx.x * 16;
    for (int i = tid; i < 16*INF; i += 256) {
        int g = i >> 7, k = i & 127;
        sin_[g][k] = in[(size_t)(node0+g)*INF + k];
    }
    __syncthreads();

    int gq = tid >> 6, f = tid & 63;
    int lane = tid & 31, w2 = (tid >> 5) & 1;

#pragma unroll
    for (int ng = 0; ng < 4; ng++) {
        int g = ng*4 + gq;
        int node = node0 + g;
        float acc = 0.f;
#pragma unroll
        for (int k = 0; k < INF; k++)
            acc = fmaf(sin_[g][k], sW[k*OUTF + f], acc);
        g_xw[(size_t)node*OUTF + f] = acc;

        float e = emb[(size_t)node*OUTF + f];
        float c1 = e*sa[f]       + acc*sa[64  + f];
        float c2 = e*sa[128 + f] + acc*sa[192 + f];
#pragma unroll
        for (int o = 16; o > 0; o >>= 1) {
            c1 += __shfl_down_sync(0xffffffffu, c1, o);
            c2 += __shfl_down_sync(0xffffffffu, c2, o);
        }
        if (lane == 0) { sr1[g][w2] = c1; sr2[g][w2] = c2; }
    }
    __syncthreads();
    if (tid < 16) {
        g_s1[node0 + tid] = sr1[tid][0] + sr1[tid][1];
        g_s2[node0 + tid] = sr2[tid][0] + sr2[tid][1];
    }
}

// ---------------- K_rank: replace bitonic sort with counting ranks ---------
// grid (16, BB), 128 threads. Unique 64-bit keys make ties impossible.
__global__ void k_rank()
{
    __shared__ __align__(16) unsigned long long keys[NN];  // 16 KB
    __shared__ float vals[NN];                              // 8 KB
    __shared__ float red[4];

    int b = blockIdx.y, tid = threadIdx.x;

    float m = -3.4e38f;
    for (int i = tid; i < NN; i += 128) {
        float v = g_s2[b*NN + i];
        vals[i] = v;
        unsigned u = __float_as_uint(v);
        u = u ^ (((unsigned)((int)u >> 31)) | 0x80000000u);  // order-preserving
        keys[i] = ((unsigned long long)u << 11) | (unsigned)i;
        m = fmaxf(m, v);
    }
#pragma unroll
    for (int o = 16; o > 0; o >>= 1)
        m = fmaxf(m, __shfl_xor_sync(0xffffffffu, m, o));
    if ((tid & 31) == 0) red[tid >> 5] = m;
    __syncthreads();
    float c2 = fmaxf(fmaxf(red[0], red[1]), fmaxf(red[2], red[3]));
    if (blockIdx.x == 0 && tid == 0) g_c2[b] = c2;

    int i = blockIdx.x * 128 + tid;
    float x = vals[i];
    g_E[b*NN + i] = expf(x - c2);
    g_F[b*NN + i] = expf(ALPHA*x - c2);

    unsigned long long mykey = keys[i];
    int cnt = 0;
    const ulonglong2* p2 = (const ulonglong2*)keys;
#pragma unroll 8
    for (int j2 = 0; j2 < NN/2; j2++) {
        ulonglong2 kk = p2[j2];
        cnt += (kk.x < mykey);
        cnt += (kk.y < mykey);
    }
    g_s2s [b*NN + cnt] = x;
    g_perm[b*NN + cnt] = i;
}

// ---------------- kA: per-chunk vector partial sums (reads xw via perm) ----
__global__ void kA_partial()
{
    __shared__ float Es[CROWS], Fs[CROWS];
    __shared__ int   pm[CROWS];
    __shared__ float psE[4][OUTF], psF[4][OUTF];
    int b = blockIdx.y, c = blockIdx.x, tid = threadIdx.x;
    float c2 = g_c2[b];
    if (tid < CROWS) {
        float v = g_s2s[b*NN + c*CROWS + tid];
        Es[tid] = expf(v - c2);
        Fs[tid] = expf(ALPHA*v - c2);
        pm[tid] = g_perm[b*NN + c*CROWS + tid];
    }
    __syncthreads();
    int g = tid >> 6, f = tid & 63;
    const float* xw = g_xw + (size_t)b*NN*OUTF;
    float aE = 0.f, aF = 0.f;
    int r0 = g * GROWS;
#pragma unroll
    for (int r = r0; r < r0 + GROWS; r++) {
        float x = xw[(size_t)pm[r]*OUTF + f];
        aE = fmaf(Es[r], x, aE);
        aF = fmaf(Fs[r], x, aF);
    }
    psE[g][f] = aE; psF[g][f] = aF;
    __syncthreads();
    if (tid < OUTF) {
        g_CSE[(b*CHUNKS + c)*OUTF + tid] = psE[0][tid]+psE[1][tid]+psE[2][tid]+psE[3][tid];
    } else if (tid < 2*OUTF) {
        int ff = tid - OUTF;
        g_CSF[(b*CHUNKS + c)*OUTF + ff] = psF[0][ff]+psF[1][ff]+psF[2][ff]+psF[3][ff];
    }
}

// ---------------- kC: final scan → SXE (suffix E*x), PXF (prefix F*x) ------
__global__ void kC_scan()
{
    __shared__ float Es[CROWS], Fs[CROWS];
    __shared__ int   pm[CROWS];
    __shared__ float psE[4][OUTF], psF[4][OUTF];
    int b = blockIdx.y, c = blockIdx.x, tid = threadIdx.x;
    float c2 = g_c2[b];
    if (tid < CROWS) {
        float v = g_s2s[b*NN + c*CROWS + tid];
        Es[tid] = expf(v - c2);
        Fs[tid] = expf(ALPHA*v - c2);
        pm[tid] = g_perm[b*NN + c*CROWS + tid];
    }
    __syncthreads();
    int g = tid >> 6, f = tid & 63;
    const float* xw = g_xw + (size_t)b*NN*OUTF;
    float aE = 0.f, aF = 0.f;
    float xr[GROWS];
    int r0 = g * GROWS;
#pragma unroll
    for (int r = r0; r < r0 + GROWS; r++) {
        float x = xw[(size_t)pm[r]*OUTF + f];
        xr[r - r0] = x;
        aE = fmaf(Es[r], x, aE);
        aF = fmaf(Fs[r], x, aF);
    }
    psE[g][f] = aE; psF[g][f] = aF;
    __syncthreads();

    float offE = 0.f, offF = 0.f, totE = 0.f;
#pragma unroll
    for (int cc = 0; cc < CHUNKS; cc++) {
        float vE = g_CSE[(b*CHUNKS + cc)*OUTF + f];
        float vF = g_CSF[(b*CHUNKS + cc)*OUTF + f];
        totE += vE;
        if (cc < c) { offE += vE; offF += vF; }
    }
#pragma unroll
    for (int gg = 0; gg < 3; gg++)
        if (gg < g) { offE += psE[gg][f]; offF += psF[gg][f]; }

    float* SXE = g_SXE + (size_t)b*(NN+1)*OUTF;
    float* PXF = g_PXF + (size_t)b*(NN+1)*OUTF;
    float runE = offE, runF = offF;
#pragma unroll
    for (int r = r0; r < r0 + GROWS; r++) {
        int R = c*CROWS + r;
        float x = xr[r - r0];
        SXE[(size_t)R*OUTF + f] = totE - runE;   // suffix including row R
        runE = fmaf(Es[r], x, runE);
        runF = fmaf(Fs[r], x, runF);
        PXF[(size_t)(R+1)*OUTF + f] = runF;      // prefix through row R
    }
    if (c == CHUNKS-1 && tid < OUTF) SXE[(size_t)NN*OUTF + tid] = 0.f;
    if (c == 0 && tid < OUTF)        PXF[tid] = 0.f;
}

// ---------------- k_search: scalar prefix + c1 + binary search + Z ---------
// grid BB, 256 threads. Prefix arrays live in smem only.
__global__ void k_search()
{
    __shared__ float s2sl[NN];        // 8 KB
    __shared__ float pE[NN+1], pF[NN+1];   // 16.4 KB
    __shared__ float wsE[8], wsF[8], red[8];
    int b = blockIdx.x, tid = threadIdx.x;
    float c2 = g_c2[b];
    for (int i = tid; i < NN; i += 256) s2sl[i] = g_s2s[b*NN + i];
    __syncthreads();

    float ev[8], fv[8];
    float sE = 0.f, sF = 0.f;
    int base = tid*8;
#pragma unroll
    for (int r = 0; r < 8; r++) {
        float v = s2sl[base + r];
        ev[r] = expf(v - c2); fv[r] = expf(ALPHA*v - c2);
        sE += ev[r]; sF += fv[r];
    }
    float iE = sE, iF = sF;
    int lane = tid & 31, warp = tid >> 5;
#pragma unroll
    for (int o = 1; o < 32; o <<= 1) {
        float tE = __shfl_up_sync(0xffffffffu, iE, o);
        float tF = __shfl_up_sync(0xffffffffu, iF, o);
        if (lane >= o) { iE += tE; iF += tF; }
    }
    if (lane == 31) { wsE[warp] = iE; wsF[warp] = iF; }
    __syncthreads();
    float oE = 0.f, oF = 0.f;
#pragma unroll
    for (int w = 0; w < 8; w++)
        if (w < warp) { oE += wsE[w]; oF += wsF[w]; }
    float rE = oE + iE - sE, rF = oF + iF - sF;   // exclusive offsets
#pragma unroll
    for (int r = 0; r < 8; r++) {
        pE[base + r] = rE; pF[base + r] = rF;
        rE += ev[r]; rF += fv[r];
    }
    if (tid == 255) { pE[NN] = rE; pF[NN] = rF; }

    // c1 = max over s1
    float m = -3.4e38f;
    for (int i = tid; i < NN; i += 256) m = fmaxf(m, g_s1[b*NN + i]);
#pragma unroll
    for (int o = 16; o > 0; o >>= 1)
        m = fmaxf(m, __shfl_xor_sync(0xffffffffu, m, o));
    if (lane == 0) red[warp] = m;
    __syncthreads();                  // also covers pE/pF writes above
    float c1 = red[0];
#pragma unroll
    for (int w = 1; w < 8; w++) c1 = fmaxf(c1, red[w]);
    float totE = pE[NN];

#pragma unroll
    for (int q = 0; q < 8; q++) {
        int node = b*NN + tid*8 + q;
        float s1 = g_s1[node];
        float t = -s1;
        int lo = 0, hi = NN;
        while (lo < hi) { int mid = (lo + hi) >> 1; if (s2sl[mid] < t) lo = mid + 1; else hi = mid; }
        int k = lo;
        float A  = expf(s1 - c1);
        float Bv = expf(ALPHA*s1 - c1);
        float Z  = A * (totE - pE[k]) + Bv * pF[k];
        float invZ = 1.0f / Z;
        g_An[node] = A * invZ;
        g_Bn[node] = Bv * invZ;
        g_ki[node] = k;
    }
}

// ---------------- K4: h_prime + attention (fused, 16 nodes / CTA) ----------
__global__ void k4_out(float* __restrict__ out_h, float* __restrict__ out_att)
{
    __shared__ float sE[NN], sF[NN], ss2[NN];   // 24 KB
    __shared__ float sAn[16], sBn[16], sT[16];
    __shared__ int   sK[16];
    int tid = threadIdx.x;
    int i0 = blockIdx.x * 16;
    int b = i0 >> 11;
    for (int i = tid; i < NN; i += 256) {
        sE[i]  = g_E [b*NN + i];
        sF[i]  = g_F [b*NN + i];
        ss2[i] = g_s2[b*NN + i];
    }
    if (tid < 16) {
        int node = i0 + tid;
        sAn[tid] = g_An[node]; sBn[tid] = g_Bn[node];
        sT[tid]  = -g_s1[node]; sK[tid] = g_ki[node];
    }
    __syncthreads();

    // h_prime = relu(An*SXE[k] + Bn*PXF[k]) — 1024 elements
#pragma unroll
    for (int e = tid; e < 16*OUTF; e += 256) {
        int g = e >> 6, f = e & 63;
        size_t basebk = ((size_t)b*(NN+1) + sK[g])*OUTF + f;
        float h = sAn[g]*g_SXE[basebk] + sBn[g]*g_PXF[basebk];
        out_h[(size_t)(i0 + g)*OUTF + f] = fmaxf(h, 0.f);
    }

    // attention rows (store-bound)
#pragma unroll
    for (int g = 0; g < 16; g++) {
        float Ai = sAn[g], Bi = sBn[g], t = sT[g];
        float4* dst = reinterpret_cast<float4*>(out_att + (size_t)(i0 + g) * NN);
#pragma unroll
        for (int j4 = tid; j4 < NN/4; j4 += 256) {
            int j = j4 * 4;
            float4 o;
            o.x = (ss2[j+0] >= t) ? Ai*sE[j+0] : Bi*sF[j+0];
            o.y = (ss2[j+1] >= t) ? Ai*sE[j+1] : Bi*sF[j+1];
            o.z = (ss2[j+2] >= t) ? Ai*sE[j+2] : Bi*sF[j+2];
            o.w = (ss2[j+3] >= t) ? Ai*sE[j+3] : Bi*sF[j+3];
            dst[j4] = o;
        }
    }
}

// ---------------- launch ----------------------------------------------------
extern "C" void kernel_launch(void* const* d_in, const int* in_sizes, int n_in,
                              void* d_out, int out_size)
{
    const float* in  = (const float*)d_in[0];   // (8,2048,128)
    const float* emb = (const float*)d_in[1];   // (8,2048,64)
    const float* W   = (const float*)d_in[2];   // (128,64)
    const float* a   = (const float*)d_in[3];   // (256,1)

    float* out    = (float*)d_out;
    float* out_h  = out;                          // relu(h_prime): BN*OUTF
    float* out_at = out + (size_t)BN*OUTF;        // attention:     BN*NN

    k1_xw     <<<BN/16,           256>>>(in, emb, W, a);
    k_rank    <<<dim3(16,BB),     128>>>();
    kA_partial<<<dim3(CHUNKS,BB), 256>>>();
    kC_scan   <<<dim3(CHUNKS,BB), 256>>>();
    k_search  <<<BB,              256>>>();
    k4_out    <<<BN/16,           256>>>(out_h, out_at);
}

// round 4
// speedup vs baseline: 1.8674x; 1.4606x over previous
#include <cuda_runtime.h>
#include <math.h>
#include <stdint.h>

#define ALPHA 0.2f
#define BB   8
#define NN   2048
#define INF  128
#define OUTF 64
#define BN   (BB*NN)   // 16384

#define CHUNKS 32      // chunks per batch for hierarchical scan
#define CROWS  64      // rows per chunk
#define GROUPS 8       // thread groups per chunk CTA (512 threads)
#define GROWS  8       // rows per thread in scan

// ---------------- scratch (device globals; no allocation allowed) ----------
__device__ float g_xw [BN*OUTF];          // x_w, original order
__device__ float g_s1 [BN];
__device__ float g_s2 [BN];
__device__ float g_E  [BN];               // exp(s2 - c2), original order
__device__ float g_F  [BN];               // exp(a*s2 - c2), original order
__device__ float g_s2s[BN];               // s2 sorted ascending (per batch)
__device__ int   g_perm[BN];              // sorted rank -> original index
__device__ float g_SXE[BB*(NN+1)*OUTF];   // suffix sums of E*x_w (sorted order)
__device__ float g_PXF[BB*(NN+1)*OUTF];   // prefix sums of F*x_w (exclusive)
__device__ float g_CSE[BB*CHUNKS*OUTF];   // per-chunk vector sums (E)
__device__ float g_CSF[BB*CHUNKS*OUTF];   // per-chunk vector sums (F)
__device__ float g_c2 [BB];
__device__ float g_An [BN];               // A_i * invZ_i
__device__ float g_Bn [BN];               // B_i * invZ_i
__device__ int   g_ki [BN];               // split index per node

// ---------------- K1: x_w = inputs @ W ; s1, s2  (16 nodes / CTA) ----------
// Inner loop: 4 W-values in registers, float4 broadcast of inputs, 4 nodes per
// thread -> 8 LSU instructions per 16 FMA (was 32).
__global__ void k1_xw(const float* __restrict__ in,
                      const float* __restrict__ emb,
                      const float* __restrict__ W,
                      const float* __restrict__ a)
{
    __shared__ float sW[INF*OUTF];                 // 32 KB
    __shared__ float sa[4*OUTF];                   // 1 KB
    __shared__ __align__(16) float sin_[16][INF];  // 8 KB
    __shared__ float sr1[16][2], sr2[16][2];

    int tid = threadIdx.x;
    for (int i = tid; i < INF*OUTF; i += 256) sW[i] = W[i];
    sa[tid] = a[tid];
    int node0 = blockIdx.x * 16;
    {
        // vectorized staging of 16 input rows (16*128 floats = 512 float4)
        const float4* src = (const float4*)(in + (size_t)node0*INF);
        float4* dst = (float4*)&sin_[0][0];
        for (int i = tid; i < 16*INF/4; i += 256) dst[i] = src[i];
    }
    __syncthreads();

    int gq = tid >> 6, f = tid & 63;
    int lane = tid & 31, w2 = (tid >> 5) & 1;

    float acc[4] = {0.f, 0.f, 0.f, 0.f};
#pragma unroll
    for (int kc = 0; kc < INF; kc += 4) {
        float w0 = sW[(kc+0)*OUTF + f];
        float w1 = sW[(kc+1)*OUTF + f];
        float w2v = sW[(kc+2)*OUTF + f];
        float w3 = sW[(kc+3)*OUTF + f];
#pragma unroll
        for (int ng = 0; ng < 4; ng++) {
            float4 s4 = *(const float4*)&sin_[ng*4 + gq][kc];
            acc[ng] = fmaf(s4.x, w0, acc[ng]);
            acc[ng] = fmaf(s4.y, w1, acc[ng]);
            acc[ng] = fmaf(s4.z, w2v, acc[ng]);
            acc[ng] = fmaf(s4.w, w3, acc[ng]);
        }
    }

#pragma unroll
    for (int ng = 0; ng < 4; ng++) {
        int g = ng*4 + gq;
        int node = node0 + g;
        g_xw[(size_t)node*OUTF + f] = acc[ng];

        float e = emb[(size_t)node*OUTF + f];
        float c1 = e*sa[f]       + acc[ng]*sa[64  + f];
        float c2 = e*sa[128 + f] + acc[ng]*sa[192 + f];
#pragma unroll
        for (int o = 16; o > 0; o >>= 1) {
            c1 += __shfl_down_sync(0xffffffffu, c1, o);
            c2 += __shfl_down_sync(0xffffffffu, c2, o);
        }
        if (lane == 0) { sr1[g][w2] = c1; sr2[g][w2] = c2; }
    }
    __syncthreads();
    if (tid < 16) {
        g_s1[node0 + tid] = sr1[tid][0] + sr1[tid][1];
        g_s2[node0 + tid] = sr2[tid][0] + sr2[tid][1];
    }
}

// ---------------- K_rank: counting ranks (replaces sort) -------------------
// grid (16, BB), 128 threads. Unique 64-bit keys make ties impossible.
__global__ void k_rank()
{
    __shared__ __align__(16) unsigned long long keys[NN];  // 16 KB
    __shared__ float vals[NN];                              // 8 KB
    __shared__ float red[4];

    int b = blockIdx.y, tid = threadIdx.x;

    float m = -3.4e38f;
    for (int i = tid; i < NN; i += 128) {
        float v = g_s2[b*NN + i];
        vals[i] = v;
        unsigned u = __float_as_uint(v);
        u = u ^ (((unsigned)((int)u >> 31)) | 0x80000000u);  // order-preserving
        keys[i] = ((unsigned long long)u << 11) | (unsigned)i;
        m = fmaxf(m, v);
    }
#pragma unroll
    for (int o = 16; o > 0; o >>= 1)
        m = fmaxf(m, __shfl_xor_sync(0xffffffffu, m, o));
    if ((tid & 31) == 0) red[tid >> 5] = m;
    __syncthreads();
    float c2 = fmaxf(fmaxf(red[0], red[1]), fmaxf(red[2], red[3]));
    if (blockIdx.x == 0 && tid == 0) g_c2[b] = c2;

    int i = blockIdx.x * 128 + tid;
    float x = vals[i];
    g_E[b*NN + i] = expf(x - c2);
    g_F[b*NN + i] = expf(ALPHA*x - c2);

    unsigned long long mykey = keys[i];
    int cnt = 0;
    const ulonglong2* p2 = (const ulonglong2*)keys;
#pragma unroll 8
    for (int j2 = 0; j2 < NN/2; j2++) {
        ulonglong2 kk = p2[j2];
        cnt += (kk.x < mykey);
        cnt += (kk.y < mykey);
    }
    g_s2s [b*NN + cnt] = x;
    g_perm[b*NN + cnt] = i;
}

// ---------------- kA: per-chunk vector partial sums (512 thr) --------------
__global__ void kA_partial()
{
    __shared__ float Es[CROWS], Fs[CROWS];
    __shared__ int   pm[CROWS];
    __shared__ float psE[GROUPS][OUTF], psF[GROUPS][OUTF];
    int b = blockIdx.y, c = blockIdx.x, tid = threadIdx.x;
    float c2 = g_c2[b];
    if (tid < CROWS) {
        float v = g_s2s[b*NN + c*CROWS + tid];
        Es[tid] = expf(v - c2);
        Fs[tid] = expf(ALPHA*v - c2);
        pm[tid] = g_perm[b*NN + c*CROWS + tid];
    }
    __syncthreads();
    int g = tid >> 6, f = tid & 63;
    const float* xw = g_xw + (size_t)b*NN*OUTF;
    float aE = 0.f, aF = 0.f;
    int r0 = g * GROWS;
#pragma unroll
    for (int r = r0; r < r0 + GROWS; r++) {
        float x = xw[(size_t)pm[r]*OUTF + f];
        aE = fmaf(Es[r], x, aE);
        aF = fmaf(Fs[r], x, aF);
    }
    psE[g][f] = aE; psF[g][f] = aF;
    __syncthreads();
    if (tid < OUTF) {
        float s = 0.f;
#pragma unroll
        for (int gg = 0; gg < GROUPS; gg++) s += psE[gg][tid];
        g_CSE[(b*CHUNKS + c)*OUTF + tid] = s;
    } else if (tid < 2*OUTF) {
        int ff = tid - OUTF;
        float s = 0.f;
#pragma unroll
        for (int gg = 0; gg < GROUPS; gg++) s += psF[gg][ff];
        g_CSF[(b*CHUNKS + c)*OUTF + ff] = s;
    }
}

// ---------------- kC: final scan → SXE (suffix E*x), PXF (prefix F*x) ------
__global__ void kC_scan()
{
    __shared__ float Es[CROWS], Fs[CROWS];
    __shared__ int   pm[CROWS];
    __shared__ float psE[GROUPS][OUTF], psF[GROUPS][OUTF];
    int b = blockIdx.y, c = blockIdx.x, tid = threadIdx.x;
    float c2 = g_c2[b];
    if (tid < CROWS) {
        float v = g_s2s[b*NN + c*CROWS + tid];
        Es[tid] = expf(v - c2);
        Fs[tid] = expf(ALPHA*v - c2);
        pm[tid] = g_perm[b*NN + c*CROWS + tid];
    }
    __syncthreads();
    int g = tid >> 6, f = tid & 63;
    const float* xw = g_xw + (size_t)b*NN*OUTF;
    float aE = 0.f, aF = 0.f;
    float xr[GROWS];
    int r0 = g * GROWS;
#pragma unroll
    for (int r = r0; r < r0 + GROWS; r++) {
        float x = xw[(size_t)pm[r]*OUTF + f];
        xr[r - r0] = x;
        aE = fmaf(Es[r], x, aE);
        aF = fmaf(Fs[r], x, aF);
    }
    psE[g][f] = aE; psF[g][f] = aF;
    __syncthreads();

    float offE = 0.f, offF = 0.f, totE = 0.f;
#pragma unroll
    for (int cc = 0; cc < CHUNKS; cc++) {
        float vE = g_CSE[(b*CHUNKS + cc)*OUTF + f];
        float vF = g_CSF[(b*CHUNKS + cc)*OUTF + f];
        totE += vE;
        if (cc < c) { offE += vE; offF += vF; }
    }
#pragma unroll
    for (int gg = 0; gg < GROUPS-1; gg++)
        if (gg < g) { offE += psE[gg][f]; offF += psF[gg][f]; }

    float* SXE = g_SXE + (size_t)b*(NN+1)*OUTF;
    float* PXF = g_PXF + (size_t)b*(NN+1)*OUTF;
    float runE = offE, runF = offF;
#pragma unroll
    for (int r = r0; r < r0 + GROWS; r++) {
        int R = c*CROWS + r;
        float x = xr[r - r0];
        SXE[(size_t)R*OUTF + f] = totE - runE;   // suffix including row R
        runE = fmaf(Es[r], x, runE);
        runF = fmaf(Fs[r], x, runF);
        PXF[(size_t)(R+1)*OUTF + f] = runF;      // prefix through row R
    }
    if (c == CHUNKS-1 && tid < OUTF) SXE[(size_t)NN*OUTF + tid] = 0.f;
    if (c == 0 && tid < OUTF)        PXF[tid] = 0.f;
}

// ---------------- k_search: scalar prefix + c1 + binary search + Z ---------
// grid BB, 512 threads. Prefix arrays live in smem only.
__global__ void k_search()
{
    __shared__ float s2sl[NN];             // 8 KB
    __shared__ float pE[NN+1], pF[NN+1];   // 16.4 KB
    __shared__ float wsE[16], wsF[16], red[16];
    int b = blockIdx.x, tid = threadIdx.x;
    float c2 = g_c2[b];
    for (int i = tid; i < NN; i += 512) s2sl[i] = g_s2s[b*NN + i];
    __syncthreads();

    float ev[4], fv[4];
    float sE = 0.f, sF = 0.f;
    int base = tid*4;
#pragma unroll
    for (int r = 0; r < 4; r++) {
        float v = s2sl[base + r];
        ev[r] = expf(v - c2); fv[r] = expf(ALPHA*v - c2);
        sE += ev[r]; sF += fv[r];
    }
    float iE = sE, iF = sF;
    int lane = tid & 31, warp = tid >> 5;
#pragma unroll
    for (int o = 1; o < 32; o <<= 1) {
        float tE = __shfl_up_sync(0xffffffffu, iE, o);
        float tF = __shfl_up_sync(0xffffffffu, iF, o);
        if (lane >= o) { iE += tE; iF += tF; }
    }
    if (lane == 31) { wsE[warp] = iE; wsF[warp] = iF; }
    __syncthreads();
    float oE = 0.f, oF = 0.f;
#pragma unroll
    for (int w = 0; w < 16; w++)
        if (w < warp) { oE += wsE[w]; oF += wsF[w]; }
    float rE = oE + iE - sE, rF = oF + iF - sF;   // exclusive offsets
#pragma unroll
    for (int r = 0; r < 4; r++) {
        pE[base + r] = rE; pF[base + r] = rF;
        rE += ev[r]; rF += fv[r];
    }
    if (tid == 511) { pE[NN] = rE; pF[NN] = rF; }

    // c1 = max over s1
    float m = -3.4e38f;
    for (int i = tid; i < NN; i += 512) m = fmaxf(m, g_s1[b*NN + i]);
#pragma unroll
    for (int o = 16; o > 0; o >>= 1)
        m = fmaxf(m, __shfl_xor_sync(0xffffffffu, m, o));
    if (lane == 0) red[warp] = m;
    __syncthreads();                  // also covers pE/pF writes above
    float c1 = red[0];
#pragma unroll
    for (int w = 1; w < 16; w++) c1 = fmaxf(c1, red[w]);
    float totE = pE[NN];

#pragma unroll
    for (int q = 0; q < 4; q++) {
        int node = b*NN + tid*4 + q;
        float s1 = g_s1[node];
        float t = -s1;
        int lo = 0, hi = NN;
        while (lo < hi) { int mid = (lo + hi) >> 1; if (s2sl[mid] < t) lo = mid + 1; else hi = mid; }
        int k = lo;
        float A  = expf(s1 - c1);
        float Bv = expf(ALPHA*s1 - c1);
        float Z  = A * (totE - pE[k]) + Bv * pF[k];
        float invZ = 1.0f / Z;
        g_An[node] = A * invZ;
        g_Bn[node] = Bv * invZ;
        g_ki[node] = k;
    }
}

// ---------------- K4: h_prime + attention (fused, 16 nodes / CTA) ----------
__global__ void k4_out(float* __restrict__ out_h, float* __restrict__ out_att)
{
    __shared__ float sE[NN], sF[NN], ss2[NN];   // 24 KB
    __shared__ float sAn[16], sBn[16], sT[16];
    __shared__ int   sK[16];
    int tid = threadIdx.x;
    int i0 = blockIdx.x * 16;
    int b = i0 >> 11;
    for (int i = tid; i < NN; i += 256) {
        sE[i]  = g_E [b*NN + i];
        sF[i]  = g_F [b*NN + i];
        ss2[i] = g_s2[b*NN + i];
    }
    if (tid < 16) {
        int node = i0 + tid;
        sAn[tid] = g_An[node]; sBn[tid] = g_Bn[node];
        sT[tid]  = -g_s1[node]; sK[tid] = g_ki[node];
    }
    __syncthreads();

    // h_prime = relu(An*SXE[k] + Bn*PXF[k]) — 1024 elements
#pragma unroll
    for (int e = tid; e < 16*OUTF; e += 256) {
        int g = e >> 6, f = e & 63;
        size_t basebk = ((size_t)b*(NN+1) + sK[g])*OUTF + f;
        float h = sAn[g]*g_SXE[basebk] + sBn[g]*g_PXF[basebk];
        out_h[(size_t)(i0 + g)*OUTF + f] = fmaxf(h, 0.f);
    }

    // attention rows (store-bound)
#pragma unroll
    for (int g = 0; g < 16; g++) {
        float Ai = sAn[g], Bi = sBn[g], t = sT[g];
        float4* dst = reinterpret_cast<float4*>(out_att + (size_t)(i0 + g) * NN);
#pragma unroll
        for (int j4 = tid; j4 < NN/4; j4 += 256) {
            int j = j4 * 4;
            float4 o;
            o.x = (ss2[j+0] >= t) ? Ai*sE[j+0] : Bi*sF[j+0];
            o.y = (ss2[j+1] >= t) ? Ai*sE[j+1] : Bi*sF[j+1];
            o.z = (ss2[j+2] >= t) ? Ai*sE[j+2] : Bi*sF[j+2];
            o.w = (ss2[j+3] >= t) ? Ai*sE[j+3] : Bi*sF[j+3];
            dst[j4] = o;
        }
    }
}

// ---------------- launch ----------------------------------------------------
extern "C" void kernel_launch(void* const* d_in, const int* in_sizes, int n_in,
                              void* d_out, int out_size)
{
    const float* in  = (const float*)d_in[0];   // (8,2048,128)
    const float* emb = (const float*)d_in[1];   // (8,2048,64)
    const float* W   = (const float*)d_in[2];   // (128,64)
    const float* a   = (const float*)d_in[3];   // (256,1)

    float* out    = (float*)d_out;
    float* out_h  = out;                          // relu(h_prime): BN*OUTF
    float* out_at = out + (size_t)BN*OUTF;        // attention:     BN*NN

    k1_xw     <<<BN/16,           256>>>(in, emb, W, a);
    k_rank    <<<dim3(16,BB),     128>>>();
    kA_partial<<<dim3(CHUNKS,BB), 512>>>();
    kC_scan   <<<dim3(CHUNKS,BB), 512>>>();
    k_search  <<<BB,              512>>>();
    k4_out    <<<BN/16,           256>>>(out_h, out_at);
}

// round 8
// speedup vs baseline: 2.1922x; 1.1739x over previous
#include <cuda_runtime.h>
#include <math.h>
#include <stdint.h>

#define ALPHA 0.2f
#define BB   8
#define NN   2048
#define INF  128
#define OUTF 64
#define BN   (BB*NN)   // 16384

#define CHUNKS 32      // chunks per batch for hierarchical scan
#define CROWS  64      // rows per chunk
#define GROUPS 8       // thread groups per chunk CTA (512 threads)
#define GROWS  8       // rows per thread in scan

// ---------------- scratch (device globals; no allocation allowed) ----------
__device__ float g_xw [BN*OUTF];          // x_w, original order
__device__ float g_s1 [BN];
__device__ float g_s2 [BN];
__device__ float g_E  [BN];               // exp(s2 - c2), original order
__device__ float g_F  [BN];               // exp(a*s2 - c2), original order
__device__ float g_s2s[BN];               // s2 sorted ascending (per batch)
__device__ int   g_perm[BN];              // sorted rank -> original index
__device__ float g_SXE[BB*(NN+1)*OUTF];   // suffix sums of E*x_w (sorted order)
__device__ float g_PXF[BB*(NN+1)*OUTF];   // prefix sums of F*x_w (exclusive)
__device__ float g_CSE[BB*CHUNKS*OUTF];   // per-chunk vector sums (E)
__device__ float g_CSF[BB*CHUNKS*OUTF];   // per-chunk vector sums (F)
__device__ float g_c2 [BB];
__device__ float g_An [BN];               // A_i * invZ_i
__device__ float g_Bn [BN];               // B_i * invZ_i
__device__ int   g_ki [BN];               // split index per node

// ---------------- K1: x_w = inputs @ W ; s1, s2  (16 nodes / CTA) ----------
__global__ void k1_xw(const float* __restrict__ in,
                      const float* __restrict__ emb,
                      const float* __restrict__ W,
                      const float* __restrict__ a)
{
    __shared__ float sW[INF*OUTF];                 // 32 KB
    __shared__ float sa[4*OUTF];                   // 1 KB
    __shared__ __align__(16) float sin_[16][INF];  // 8 KB
    __shared__ float sr1[16][2], sr2[16][2];

    int tid = threadIdx.x;
    for (int i = tid; i < INF*OUTF; i += 256) sW[i] = W[i];
    sa[tid] = a[tid];
    int node0 = blockIdx.x * 16;
    {
        const float4* src = (const float4*)(in + (size_t)node0*INF);
        float4* dst = (float4*)&sin_[0][0];
        for (int i = tid; i < 16*INF/4; i += 256) dst[i] = src[i];
    }
    __syncthreads();

    int gq = tid >> 6, f = tid & 63;
    int lane = tid & 31, w2 = (tid >> 5) & 1;

    float acc[4] = {0.f, 0.f, 0.f, 0.f};
#pragma unroll
    for (int kc = 0; kc < INF; kc += 4) {
        float w0 = sW[(kc+0)*OUTF + f];
        float w1 = sW[(kc+1)*OUTF + f];
        float w2v = sW[(kc+2)*OUTF + f];
        float w3 = sW[(kc+3)*OUTF + f];
#pragma unroll
        for (int ng = 0; ng < 4; ng++) {
            float4 s4 = *(const float4*)&sin_[ng*4 + gq][kc];
            acc[ng] = fmaf(s4.x, w0, acc[ng]);
            acc[ng] = fmaf(s4.y, w1, acc[ng]);
            acc[ng] = fmaf(s4.z, w2v, acc[ng]);
            acc[ng] = fmaf(s4.w, w3, acc[ng]);
        }
    }

#pragma unroll
    for (int ng = 0; ng < 4; ng++) {
        int g = ng*4 + gq;
        int node = node0 + g;
        g_xw[(size_t)node*OUTF + f] = acc[ng];

        float e = emb[(size_t)node*OUTF + f];
        float c1 = e*sa[f]       + acc[ng]*sa[64  + f];
        float c2 = e*sa[128 + f] + acc[ng]*sa[192 + f];
#pragma unroll
        for (int o = 16; o > 0; o >>= 1) {
            c1 += __shfl_down_sync(0xffffffffu, c1, o);
            c2 += __shfl_down_sync(0xffffffffu, c2, o);
        }
        if (lane == 0) { sr1[g][w2] = c1; sr2[g][w2] = c2; }
    }
    __syncthreads();
    if (tid < 16) {
        g_s1[node0 + tid] = sr1[tid][0] + sr1[tid][1];
        g_s2[node0 + tid] = sr2[tid][0] + sr2[tid][1];
    }
}

// ---------------- K_rank: counting ranks (replaces sort) -------------------
__global__ void k_rank()
{
    __shared__ __align__(16) unsigned long long keys[NN];  // 16 KB
    __shared__ float vals[NN];                              // 8 KB
    __shared__ float red[4];

    int b = blockIdx.y, tid = threadIdx.x;

    float m = -3.4e38f;
    for (int i = tid; i < NN; i += 128) {
        float v = g_s2[b*NN + i];
        vals[i] = v;
        unsigned u = __float_as_uint(v);
        u = u ^ (((unsigned)((int)u >> 31)) | 0x80000000u);  // order-preserving
        keys[i] = ((unsigned long long)u << 11) | (unsigned)i;
        m = fmaxf(m, v);
    }
#pragma unroll
    for (int o = 16; o > 0; o >>= 1)
        m = fmaxf(m, __shfl_xor_sync(0xffffffffu, m, o));
    if ((tid & 31) == 0) red[tid >> 5] = m;
    __syncthreads();
    float c2 = fmaxf(fmaxf(red[0], red[1]), fmaxf(red[2], red[3]));
    if (blockIdx.x == 0 && tid == 0) g_c2[b] = c2;

    int i = blockIdx.x * 128 + tid;
    float x = vals[i];
    g_E[b*NN + i] = expf(x - c2);
    g_F[b*NN + i] = expf(ALPHA*x - c2);

    unsigned long long mykey = keys[i];
    int cnt = 0;
    const ulonglong2* p2 = (const ulonglong2*)keys;
#pragma unroll 8
    for (int j2 = 0; j2 < NN/2; j2++) {
        ulonglong2 kk = p2[j2];
        cnt += (kk.x < mykey);
        cnt += (kk.y < mykey);
    }
    g_s2s [b*NN + cnt] = x;
    g_perm[b*NN + cnt] = i;
}

// ---------------- kA: per-chunk vector partial sums (512 thr) --------------
__global__ void kA_partial()
{
    __shared__ float Es[CROWS], Fs[CROWS];
    __shared__ int   pm[CROWS];
    __shared__ float psE[GROUPS][OUTF], psF[GROUPS][OUTF];
    int b = blockIdx.y, c = blockIdx.x, tid = threadIdx.x;
    float c2 = g_c2[b];
    if (tid < CROWS) {
        float v = g_s2s[b*NN + c*CROWS + tid];
        Es[tid] = expf(v - c2);
        Fs[tid] = expf(ALPHA*v - c2);
        pm[tid] = g_perm[b*NN + c*CROWS + tid];
    }
    __syncthreads();
    int g = tid >> 6, f = tid & 63;
    const float* xw = g_xw + (size_t)b*NN*OUTF;
    float aE = 0.f, aF = 0.f;
    int r0 = g * GROWS;
#pragma unroll
    for (int r = r0; r < r0 + GROWS; r++) {
        float x = xw[(size_t)pm[r]*OUTF + f];
        aE = fmaf(Es[r], x, aE);
        aF = fmaf(Fs[r], x, aF);
    }
    psE[g][f] = aE; psF[g][f] = aF;
    __syncthreads();
    if (tid < OUTF) {
        float s = 0.f;
#pragma unroll
        for (int gg = 0; gg < GROUPS; gg++) s += psE[gg][tid];
        g_CSE[(b*CHUNKS + c)*OUTF + tid] = s;
    } else if (tid < 2*OUTF) {
        int ff = tid - OUTF;
        float s = 0.f;
#pragma unroll
        for (int gg = 0; gg < GROUPS; gg++) s += psF[gg][ff];
        g_CSF[(b*CHUNKS + c)*OUTF + ff] = s;
    }
}

// ---------------- kC: final scan → SXE (suffix E*x), PXF (prefix F*x) ------
__global__ void kC_scan()
{
    __shared__ float Es[CROWS], Fs[CROWS];
    __shared__ int   pm[CROWS];
    __shared__ float psE[GROUPS][OUTF], psF[GROUPS][OUTF];
    __shared__ float sCSE[CHUNKS][OUTF], sCSF[CHUNKS][OUTF];  // 16 KB staged
    int b = blockIdx.y, c = blockIdx.x, tid = threadIdx.x;
    float c2 = g_c2[b];
    if (tid < CROWS) {
        float v = g_s2s[b*NN + c*CROWS + tid];
        Es[tid] = expf(v - c2);
        Fs[tid] = expf(ALPHA*v - c2);
        pm[tid] = g_perm[b*NN + c*CROWS + tid];
    }
    // cooperative stage of chunk sums (coalesced, once per CTA)
    for (int i = tid; i < CHUNKS*OUTF; i += 512) {
        (&sCSE[0][0])[i] = g_CSE[b*CHUNKS*OUTF + i];
        (&sCSF[0][0])[i] = g_CSF[b*CHUNKS*OUTF + i];
    }
    __syncthreads();
    int g = tid >> 6, f = tid & 63;
    const float* xw = g_xw + (size_t)b*NN*OUTF;
    float aE = 0.f, aF = 0.f;
    float xr[GROWS];
    int r0 = g * GROWS;
#pragma unroll
    for (int r = r0; r < r0 + GROWS; r++) {
        float x = xw[(size_t)pm[r]*OUTF + f];
        xr[r - r0] = x;
        aE = fmaf(Es[r], x, aE);
        aF = fmaf(Fs[r], x, aF);
    }
    psE[g][f] = aE; psF[g][f] = aF;
    __syncthreads();

    float offE = 0.f, offF = 0.f, totE = 0.f;
#pragma unroll
    for (int cc = 0; cc < CHUNKS; cc++) {
        float vE = sCSE[cc][f];
        float vF = sCSF[cc][f];
        totE += vE;
        if (cc < c) { offE += vE; offF += vF; }
    }
#pragma unroll
    for (int gg = 0; gg < GROUPS-1; gg++)
        if (gg < g) { offE += psE[gg][f]; offF += psF[gg][f]; }

    float* SXE = g_SXE + (size_t)b*(NN+1)*OUTF;
    float* PXF = g_PXF + (size_t)b*(NN+1)*OUTF;
    float runE = offE, runF = offF;
#pragma unroll
    for (int r = r0; r < r0 + GROWS; r++) {
        int R = c*CROWS + r;
        float x = xr[r - r0];
        SXE[(size_t)R*OUTF + f] = totE - runE;   // suffix including row R
        runE = fmaf(Es[r], x, runE);
        runF = fmaf(Fs[r], x, runF);
        PXF[(size_t)(R+1)*OUTF + f] = runF;      // prefix through row R
    }
    if (c == CHUNKS-1 && tid < OUTF) SXE[(size_t)NN*OUTF + tid] = 0.f;
    if (c == 0 && tid < OUTF)        PXF[tid] = 0.f;
}

// ---------------- k_search: scalar prefix + c1 + search + Z  (grid 4xBB) ---
__global__ void k_search()
{
    __shared__ float s2sl[NN];             // 8 KB
    __shared__ float pE[NN+1], pF[NN+1];   // 16.4 KB
    __shared__ float wsE[16], wsF[16], red[16];
    int b = blockIdx.y, tid = threadIdx.x;
    float c2 = g_c2[b];
    for (int i = tid; i < NN; i += 512) s2sl[i] = g_s2s[b*NN + i];
    __syncthreads();

    float ev[4], fv[4];
    float sE = 0.f, sF = 0.f;
    int base = tid*4;
#pragma unroll
    for (int r = 0; r < 4; r++) {
        float v = s2sl[base + r];
        ev[r] = expf(v - c2); fv[r] = expf(ALPHA*v - c2);
        sE += ev[r]; sF += fv[r];
    }
    float iE = sE, iF = sF;
    int lane = tid & 31, warp = tid >> 5;
#pragma unroll
    for (int o = 1; o < 32; o <<= 1) {
        float tE = __shfl_up_sync(0xffffffffu, iE, o);
        float tF = __shfl_up_sync(0xffffffffu, iF, o);
        if (lane >= o) { iE += tE; iF += tF; }
    }
    if (lane == 31) { wsE[warp] = iE; wsF[warp] = iF; }
    __syncthreads();
    float oE = 0.f, oF = 0.f;
#pragma unroll
    for (int w = 0; w < 16; w++)
        if (w < warp) { oE += wsE[w]; oF += wsF[w]; }
    float rE = oE + iE - sE, rF = oF + iF - sF;   // exclusive offsets
#pragma unroll
    for (int r = 0; r < 4; r++) {
        pE[base + r] = rE; pF[base + r] = rF;
        rE += ev[r]; rF += fv[r];
    }
    if (tid == 511) { pE[NN] = rE; pF[NN] = rF; }

    // c1 = max over s1
    float m = -3.4e38f;
    for (int i = tid; i < NN; i += 512) m = fmaxf(m, g_s1[b*NN + i]);
#pragma unroll
    for (int o = 16; o > 0; o >>= 1)
        m = fmaxf(m, __shfl_xor_sync(0xffffffffu, m, o));
    if (lane == 0) red[warp] = m;
    __syncthreads();                  // also covers pE/pF writes above
    float c1 = red[0];
#pragma unroll
    for (int w = 1; w < 16; w++) c1 = fmaxf(c1, red[w]);
    float totE = pE[NN];

    // one node per thread (this CTA's 512-node segment)
    int node = b*NN + blockIdx.x*512 + tid;
    float s1 = g_s1[node];
    float t = -s1;
    int lo = 0, hi = NN;
    while (lo < hi) { int mid = (lo + hi) >> 1; if (s2sl[mid] < t) lo = mid + 1; else hi = mid; }
    int k = lo;
    float A  = expf(s1 - c1);
    float Bv = expf(ALPHA*s1 - c1);
    float Z  = A * (totE - pE[k]) + Bv * pF[k];
    float invZ = 1.0f / Z;
    g_An[node] = A * invZ;
    g_Bn[node] = Bv * invZ;
    g_ki[node] = k;
}

// ---------------- K4: h_prime + attention (fused, 16 nodes / CTA) ----------
// Column data loaded ONCE per j-chunk and reused across all 16 nodes.
__global__ void k4_out(float* __restrict__ out_h, float* __restrict__ out_att)
{
    __shared__ __align__(16) float sE[NN], sF[NN], ss2[NN];   // 24 KB
    __shared__ float sAn[16], sBn[16], sT[16];
    __shared__ int   sK[16];
    int tid = threadIdx.x;
    int i0 = blockIdx.x * 16;
    int b = i0 >> 11;
    {
        const float4* pe = (const float4*)(g_E  + b*NN);
        const float4* pf = (const float4*)(g_F  + b*NN);
        const float4* ps = (const float4*)(g_s2 + b*NN);
        float4* de = (float4*)sE; float4* df = (float4*)sF; float4* ds = (float4*)ss2;
        for (int i = tid; i < NN/4; i += 256) { de[i] = pe[i]; df[i] = pf[i]; ds[i] = ps[i]; }
    }
    if (tid < 16) {
        int node = i0 + tid;
        sAn[tid] = g_An[node]; sBn[tid] = g_Bn[node];
        sT[tid]  = -g_s1[node]; sK[tid] = g_ki[node];
    }
    __syncthreads();

    // h_prime = relu(An*SXE[k] + Bn*PXF[k]) — 1024 elements
#pragma unroll
    for (int e = tid; e < 16*OUTF; e += 256) {
        int g = e >> 6, f = e & 63;
        size_t basebk = ((size_t)b*(NN+1) + sK[g])*OUTF + f;
        float h = sAn[g]*g_SXE[basebk] + sBn[g]*g_PXF[basebk];
        out_h[(size_t)(i0 + g)*OUTF + f] = fmaxf(h, 0.f);
    }

    // attention: load columns once, write 16 node-rows (store-bound)
    const float4* e4p = (const float4*)sE;
    const float4* f4p = (const float4*)sF;
    const float4* s4p = (const float4*)ss2;
    float* outbase = out_att + (size_t)i0 * NN;
#pragma unroll
    for (int j4 = tid; j4 < NN/4; j4 += 256) {
        float4 e4 = e4p[j4], f4 = f4p[j4], s4 = s4p[j4];
#pragma unroll
        for (int g = 0; g < 16; g++) {
            float Ai = sAn[g], Bi = sBn[g], t = sT[g];
            float4 o;
            o.x = (s4.x >= t) ? Ai*e4.x : Bi*f4.x;
            o.y = (s4.y >= t) ? Ai*e4.y : Bi*f4.y;
            o.z = (s4.z >= t) ? Ai*e4.z : Bi*f4.z;
            o.w = (s4.w >= t) ? Ai*e4.w : Bi*f4.w;
            *(float4*)(outbase + (size_t)g*NN + j4*4) = o;
        }
    }
}

// ---------------- launch ----------------------------------------------------
extern "C" void kernel_launch(void* const* d_in, const int* in_sizes, int n_in,
                              void* d_out, int out_size)
{
    const float* in  = (const float*)d_in[0];   // (8,2048,128)
    const float* emb = (const float*)d_in[1];   // (8,2048,64)
    const float* W   = (const float*)d_in[2];   // (128,64)
    const float* a   = (const float*)d_in[3];   // (256,1)

    float* out    = (float*)d_out;
    float* out_h  = out;                          // relu(h_prime): BN*OUTF
    float* out_at = out + (size_t)BN*OUTF;        // attention:     BN*NN

    k1_xw     <<<BN/16,           256>>>(in, emb, W, a);
    k_rank    <<<dim3(16,BB),     128>>>();
    kA_partial<<<dim3(CHUNKS,BB), 512>>>();
    kC_scan   <<<dim3(CHUNKS,BB), 512>>>();
    k_search  <<<dim3(4,BB),      512>>>();
    k4_out    <<<BN/16,           256>>>(out_h, out_at);
}

// round 9
// speedup vs baseline: 2.3277x; 1.0618x over previous
#include <cuda_runtime.h>
#include <math.h>
#include <stdint.h>

#define ALPHA 0.2f
#define BB   8
#define NN   2048
#define INF  128
#define OUTF 64
#define BN   (BB*NN)   // 16384

#define CHUNKS 32      // chunks per batch for hierarchical scan
#define CROWS  64      // rows per chunk
#define GROUPS 8       // thread groups per chunk CTA (512 threads)
#define GROWS  8       // rows per thread in scan

#define SCAN_CTAS (CHUNKS*BB)   // 256
#define ATT_NPC   32            // nodes per attention CTA
#define ATT_CTAS  (BN/ATT_NPC)  // 512

// ---------------- scratch (device globals; no allocation allowed) ----------
__device__ float g_xw [BN*OUTF];          // x_w, original order
__device__ float g_s1 [BN];
__device__ float g_s2 [BN];
__device__ float g_E  [BN];               // exp(s2 - c2), original order
__device__ float g_F  [BN];               // exp(a*s2 - c2), original order
__device__ float g_s2s[BN];               // s2 sorted ascending (per batch)
__device__ int   g_perm[BN];              // sorted rank -> original index
__device__ float g_SXE[BB*(NN+1)*OUTF];   // suffix sums of E*x_w (sorted order)
__device__ float g_PXF[BB*(NN+1)*OUTF];   // prefix sums of F*x_w (exclusive)
__device__ float g_CSE[BB*CHUNKS*OUTF];   // per-chunk vector sums (E)
__device__ float g_CSF[BB*CHUNKS*OUTF];   // per-chunk vector sums (F)
__device__ float g_c2 [BB];
__device__ float g_An [BN];               // A_i * invZ_i
__device__ float g_Bn [BN];               // B_i * invZ_i
__device__ int   g_ki [BN];               // split index per node
__device__ int   g_cnt1[BB];              // scan phase-1 arrival counters
__device__ int   g_cnt2[BB];              // scan phase-2 arrival counters

// ---------------- K1: x_w = inputs @ W ; s1, s2  (16 nodes / CTA) ----------
__global__ void k1_xw(const float* __restrict__ in,
                      const float* __restrict__ emb,
                      const float* __restrict__ W,
                      const float* __restrict__ a)
{
    __shared__ float sW[INF*OUTF];                 // 32 KB
    __shared__ float sa[4*OUTF];                   // 1 KB
    __shared__ __align__(16) float sin_[16][INF];  // 8 KB
    __shared__ float sr1[16][2], sr2[16][2];

    int tid = threadIdx.x;
    for (int i = tid; i < INF*OUTF; i += 256) sW[i] = W[i];
    sa[tid] = a[tid];
    int node0 = blockIdx.x * 16;
    {
        const float4* src = (const float4*)(in + (size_t)node0*INF);
        float4* dst = (float4*)&sin_[0][0];
        for (int i = tid; i < 16*INF/4; i += 256) dst[i] = src[i];
    }
    __syncthreads();

    int gq = tid >> 6, f = tid & 63;
    int lane = tid & 31, w2 = (tid >> 5) & 1;

    float acc[4] = {0.f, 0.f, 0.f, 0.f};
#pragma unroll
    for (int kc = 0; kc < INF; kc += 4) {
        float w0 = sW[(kc+0)*OUTF + f];
        float w1 = sW[(kc+1)*OUTF + f];
        float w2v = sW[(kc+2)*OUTF + f];
        float w3 = sW[(kc+3)*OUTF + f];
#pragma unroll
        for (int ng = 0; ng < 4; ng++) {
            float4 s4 = *(const float4*)&sin_[ng*4 + gq][kc];
            acc[ng] = fmaf(s4.x, w0, acc[ng]);
            acc[ng] = fmaf(s4.y, w1, acc[ng]);
            acc[ng] = fmaf(s4.z, w2v, acc[ng]);
            acc[ng] = fmaf(s4.w, w3, acc[ng]);
        }
    }

#pragma unroll
    for (int ng = 0; ng < 4; ng++) {
        int g = ng*4 + gq;
        int node = node0 + g;
        g_xw[(size_t)node*OUTF + f] = acc[ng];

        float e = emb[(size_t)node*OUTF + f];
        float c1 = e*sa[f]       + acc[ng]*sa[64  + f];
        float c2 = e*sa[128 + f] + acc[ng]*sa[192 + f];
#pragma unroll
        for (int o = 16; o > 0; o >>= 1) {
            c1 += __shfl_down_sync(0xffffffffu, c1, o);
            c2 += __shfl_down_sync(0xffffffffu, c2, o);
        }
        if (lane == 0) { sr1[g][w2] = c1; sr2[g][w2] = c2; }
    }
    __syncthreads();
    if (tid < 16) {
        g_s1[node0 + tid] = sr1[tid][0] + sr1[tid][1];
        g_s2[node0 + tid] = sr2[tid][0] + sr2[tid][1];
    }
}

// ---------------- K_rank: counting ranks (replaces sort) -------------------
__global__ void k_rank()
{
    __shared__ __align__(16) unsigned long long keys[NN];  // 16 KB
    __shared__ float vals[NN];                              // 8 KB
    __shared__ float red[4];

    int b = blockIdx.y, tid = threadIdx.x;

    // reset mega-kernel counters for this replay (runs before k_mega)
    if (blockIdx.x == 0 && tid == 0) { g_cnt1[b] = 0; g_cnt2[b] = 0; }

    float m = -3.4e38f;
    for (int i = tid; i < NN; i += 128) {
        float v = g_s2[b*NN + i];
        vals[i] = v;
        unsigned u = __float_as_uint(v);
        u = u ^ (((unsigned)((int)u >> 31)) | 0x80000000u);  // order-preserving
        keys[i] = ((unsigned long long)u << 11) | (unsigned)i;
        m = fmaxf(m, v);
    }
#pragma unroll
    for (int o = 16; o > 0; o >>= 1)
        m = fmaxf(m, __shfl_xor_sync(0xffffffffu, m, o));
    if ((tid & 31) == 0) red[tid >> 5] = m;
    __syncthreads();
    float c2 = fmaxf(fmaxf(red[0], red[1]), fmaxf(red[2], red[3]));
    if (blockIdx.x == 0 && tid == 0) g_c2[b] = c2;

    int i = blockIdx.x * 128 + tid;
    float x = vals[i];
    g_E[b*NN + i] = expf(x - c2);
    g_F[b*NN + i] = expf(ALPHA*x - c2);

    unsigned long long mykey = keys[i];
    int cnt = 0;
    const ulonglong2* p2 = (const ulonglong2*)keys;
#pragma unroll 8
    for (int j2 = 0; j2 < NN/2; j2++) {
        ulonglong2 kk = p2[j2];
        cnt += (kk.x < mykey);
        cnt += (kk.y < mykey);
    }
    g_s2s [b*NN + cnt] = x;
    g_perm[b*NN + cnt] = i;
}

// ---------------- k_search: scalar prefix + c1 + search + Z  (grid 4xBB) ---
__global__ void k_search()
{
    __shared__ float s2sl[NN];             // 8 KB
    __shared__ float pE[NN+1], pF[NN+1];   // 16.4 KB
    __shared__ float wsE[16], wsF[16], red[16];
    int b = blockIdx.y, tid = threadIdx.x;
    float c2 = g_c2[b];
    for (int i = tid; i < NN; i += 512) s2sl[i] = g_s2s[b*NN + i];
    __syncthreads();

    float ev[4], fv[4];
    float sE = 0.f, sF = 0.f;
    int base = tid*4;
#pragma unroll
    for (int r = 0; r < 4; r++) {
        float v = s2sl[base + r];
        ev[r] = expf(v - c2); fv[r] = expf(ALPHA*v - c2);
        sE += ev[r]; sF += fv[r];
    }
    float iE = sE, iF = sF;
    int lane = tid & 31, warp = tid >> 5;
#pragma unroll
    for (int o = 1; o < 32; o <<= 1) {
        float tE = __shfl_up_sync(0xffffffffu, iE, o);
        float tF = __shfl_up_sync(0xffffffffu, iF, o);
        if (lane >= o) { iE += tE; iF += tF; }
    }
    if (lane == 31) { wsE[warp] = iE; wsF[warp] = iF; }
    __syncthreads();
    float oE = 0.f, oF = 0.f;
#pragma unroll
    for (int w = 0; w < 16; w++)
        if (w < warp) { oE += wsE[w]; oF += wsF[w]; }
    float rE = oE + iE - sE, rF = oF + iF - sF;   // exclusive offsets
#pragma unroll
    for (int r = 0; r < 4; r++) {
        pE[base + r] = rE; pF[base + r] = rF;
        rE += ev[r]; rF += fv[r];
    }
    if (tid == 511) { pE[NN] = rE; pF[NN] = rF; }

    // c1 = max over s1
    float m = -3.4e38f;
    for (int i = tid; i < NN; i += 512) m = fmaxf(m, g_s1[b*NN + i]);
#pragma unroll
    for (int o = 16; o > 0; o >>= 1)
        m = fmaxf(m, __shfl_xor_sync(0xffffffffu, m, o));
    if (lane == 0) red[warp] = m;
    __syncthreads();                  // also covers pE/pF writes above
    float c1 = red[0];
#pragma unroll
    for (int w = 1; w < 16; w++) c1 = fmaxf(c1, red[w]);
    float totE = pE[NN];

    int node = b*NN + blockIdx.x*512 + tid;
    float s1 = g_s1[node];
    float t = -s1;
    int lo = 0, hi = NN;
    while (lo < hi) { int mid = (lo + hi) >> 1; if (s2sl[mid] < t) lo = mid + 1; else hi = mid; }
    int k = lo;
    float A  = expf(s1 - c1);
    float Bv = expf(ALPHA*s1 - c1);
    float Z  = A * (totE - pE[k]) + Bv * pF[k];
    float invZ = 1.0f / Z;
    g_An[node] = A * invZ;
    g_Bn[node] = Bv * invZ;
    g_ki[node] = k;
}

// ---------------- k_mega: fused scan + h_prime + attention -----------------
struct ScanSmem {
    float Es[CROWS], Fs[CROWS];
    int   pm[CROWS];
    float psE[GROUPS][OUTF], psF[GROUPS][OUTF];
    float sCSE[CHUNKS][OUTF], sCSF[CHUNKS][OUTF];
};
struct AttSmem {
    float sE[NN], sF[NN], ss2[NN];
    float sAn[ATT_NPC], sBn[ATT_NPC], sT[ATT_NPC];
};

__global__ __launch_bounds__(512) void k_mega(float* __restrict__ out_h,
                                              float* __restrict__ out_att)
{
    __shared__ __align__(16) char smem_raw[
        sizeof(AttSmem) > sizeof(ScanSmem) ? sizeof(AttSmem) : sizeof(ScanSmem)];
    int bid = blockIdx.x;
    int tid = threadIdx.x;

    if (bid < SCAN_CTAS) {
        // ================= scan role: chunk c of batch b =================
        ScanSmem& S = *reinterpret_cast<ScanSmem*>(smem_raw);
        int b = bid >> 5, c = bid & 31;
        float c2 = g_c2[b];
        if (tid < CROWS) {
            float v = g_s2s[b*NN + c*CROWS + tid];
            S.Es[tid] = expf(v - c2);
            S.Fs[tid] = expf(ALPHA*v - c2);
            S.pm[tid] = g_perm[b*NN + c*CROWS + tid];
        }
        __syncthreads();
        int g = tid >> 6, f = tid & 63;
        const float* xw = g_xw + (size_t)b*NN*OUTF;
        float aE = 0.f, aF = 0.f;
        float xr[GROWS];
        int r0 = g * GROWS;
#pragma unroll
        for (int r = r0; r < r0 + GROWS; r++) {
            float x = xw[(size_t)S.pm[r]*OUTF + f];
            xr[r - r0] = x;
            aE = fmaf(S.Es[r], x, aE);
            aF = fmaf(S.Fs[r], x, aF);
        }
        S.psE[g][f] = aE; S.psF[g][f] = aF;
        __syncthreads();
        if (tid < OUTF) {
            float s = 0.f;
#pragma unroll
            for (int gg = 0; gg < GROUPS; gg++) s += S.psE[gg][tid];
            g_CSE[(b*CHUNKS + c)*OUTF + tid] = s;
        } else if (tid < 2*OUTF) {
            int ff = tid - OUTF;
            float s = 0.f;
#pragma unroll
            for (int gg = 0; gg < GROUPS; gg++) s += S.psF[gg][ff];
            g_CSF[(b*CHUNKS + c)*OUTF + ff] = s;
        }
        // phase-1 barrier across this batch's 32 chunk CTAs
        __threadfence();
        __syncthreads();
        if (tid == 0) {
            atomicAdd(&g_cnt1[b], 1);
            while (atomicAdd(&g_cnt1[b], 0) < CHUNKS) {}
        }
        __syncthreads();

        // stage all chunk sums (coalesced)
        for (int i = tid; i < CHUNKS*OUTF; i += 512) {
            (&S.sCSE[0][0])[i] = g_CSE[b*CHUNKS*OUTF + i];
            (&S.sCSF[0][0])[i] = g_CSF[b*CHUNKS*OUTF + i];
        }
        __syncthreads();

        float offE = 0.f, offF = 0.f, totE = 0.f;
#pragma unroll
        for (int cc = 0; cc < CHUNKS; cc++) {
            float vE = S.sCSE[cc][f];
            float vF = S.sCSF[cc][f];
            totE += vE;
            if (cc < c) { offE += vE; offF += vF; }
        }
#pragma unroll
        for (int gg = 0; gg < GROUPS-1; gg++)
            if (gg < g) { offE += S.psE[gg][f]; offF += S.psF[gg][f]; }

        float* SXE = g_SXE + (size_t)b*(NN+1)*OUTF;
        float* PXF = g_PXF + (size_t)b*(NN+1)*OUTF;
        float runE = offE, runF = offF;
#pragma unroll
        for (int r = r0; r < r0 + GROWS; r++) {
            int R = c*CROWS + r;
            float x = xr[r - r0];
            SXE[(size_t)R*OUTF + f] = totE - runE;
            runE = fmaf(S.Es[r], x, runE);
            runF = fmaf(S.Fs[r], x, runF);
            PXF[(size_t)(R+1)*OUTF + f] = runF;
        }
        if (c == CHUNKS-1 && tid < OUTF) SXE[(size_t)NN*OUTF + tid] = 0.f;
        if (c == 0 && tid < OUTF)        PXF[tid] = 0.f;

        // phase-2 barrier, then h_prime for this chunk's 64 nodes
        __threadfence();
        __syncthreads();
        if (tid == 0) {
            atomicAdd(&g_cnt2[b], 1);
            while (atomicAdd(&g_cnt2[b], 0) < CHUNKS) {}
        }
        __syncthreads();

#pragma unroll
        for (int e = tid; e < CROWS*OUTF; e += 512) {
            int gg = e >> 6, ff = e & 63;
            int node = b*NN + c*CROWS + gg;
            int k = g_ki[node];
            size_t basebk = ((size_t)b*(NN+1) + k)*OUTF + ff;
            float h = g_An[node]*g_SXE[basebk] + g_Bn[node]*g_PXF[basebk];
            out_h[(size_t)node*OUTF + ff] = fmaxf(h, 0.f);
        }
    } else {
        // ================= attention role: 32 nodes =================
        AttSmem& A = *reinterpret_cast<AttSmem*>(smem_raw);
        int abid = bid - SCAN_CTAS;          // 0..511
        int i0 = abid * ATT_NPC;
        int b = i0 >> 11;
        {
            const float4* pe = (const float4*)(g_E  + b*NN);
            const float4* pf = (const float4*)(g_F  + b*NN);
            const float4* ps = (const float4*)(g_s2 + b*NN);
            float4* de = (float4*)A.sE; float4* df = (float4*)A.sF; float4* ds = (float4*)A.ss2;
            for (int i = tid; i < NN/4; i += 512) { de[i] = pe[i]; df[i] = pf[i]; ds[i] = ps[i]; }
        }
        if (tid < ATT_NPC) {
            int node = i0 + tid;
            A.sAn[tid] = g_An[node]; A.sBn[tid] = g_Bn[node];
            A.sT[tid]  = -g_s1[node];
        }
        __syncthreads();

        int j4 = tid;                         // exactly NN/4 == 512 columns
        float4 e4 = ((const float4*)A.sE)[j4];
        float4 f4 = ((const float4*)A.sF)[j4];
        float4 s4 = ((const float4*)A.ss2)[j4];
        float* outbase = out_att + (size_t)i0 * NN + j4*4;
#pragma unroll
        for (int g = 0; g < ATT_NPC; g++) {
            float Ai = A.sAn[g], Bi = A.sBn[g], t = A.sT[g];
            float4 o;
            o.x = (s4.x >= t) ? Ai*e4.x : Bi*f4.x;
            o.y = (s4.y >= t) ? Ai*e4.y : Bi*f4.y;
            o.z = (s4.z >= t) ? Ai*e4.z : Bi*f4.z;
            o.w = (s4.w >= t) ? Ai*e4.w : Bi*f4.w;
            *(float4*)(outbase + (size_t)g*NN) = o;
        }
    }
}

// ---------------- launch ----------------------------------------------------
extern "C" void kernel_launch(void* const* d_in, const int* in_sizes, int n_in,
                              void* d_out, int out_size)
{
    const float* in  = (const float*)d_in[0];   // (8,2048,128)
    const float* emb = (const float*)d_in[1];   // (8,2048,64)
    const float* W   = (const float*)d_in[2];   // (128,64)
    const float* a   = (const float*)d_in[3];   // (256,1)

    float* out    = (float*)d_out;
    float* out_h  = out;                          // relu(h_prime): BN*OUTF
    float* out_at = out + (size_t)BN*OUTF;        // attention:     BN*NN

    k1_xw   <<<BN/16,               256>>>(in, emb, W, a);
    k_rank  <<<dim3(16,BB),         128>>>();
    k_search<<<dim3(4,BB),          512>>>();
    k_mega  <<<SCAN_CTAS + ATT_CTAS,512>>>(out_h, out_at);
}